// round 2
// baseline (speedup 1.0000x reference)
#include <cuda_runtime.h>

// Problem constants
#define BATCH 32
#define NN    2048
#define CC    8
#define FF    128
#define OO    128
#define K3    384          // 3 * FF
#define MT    64           // nodes per block (M tile)
#define KT    16           // K chunk staged in smem
#define NCHUNK (K3 / KT)   // 24
#define NTHREADS 128

struct Smem {
    float As[K3 * MT];       // transposed X tile: As[k][m]   (96 KB)
    float Bs[2][KT * OO];    // double-buffered W chunk       (16 KB)
};

__device__ __forceinline__ float4 f4zero() { float4 z; z.x=z.y=z.z=z.w=0.f; return z; }

__device__ __forceinline__ void stage_w(Smem& sm, int chunk, int p, int tid,
                                        const float* __restrict__ w_t,
                                        const float* __restrict__ w_r,
                                        const float* __restrict__ w_l)
{
#pragma unroll
    for (int i = 0; i < 4; ++i) {
        const int idx = tid + i * NTHREADS;     // float4 index, 0..511
        const int kk  = idx >> 5;               // row in tile (0..15)
        const int o4  = idx & 31;               // float4 column
        const int k   = chunk * KT + kk;
        const float* src = (k < FF)     ? (w_t + (size_t)k * OO)
                         : (k < 2*FF)   ? (w_r + (size_t)(k - FF) * OO)
                                        : (w_l + (size_t)(k - 2*FF) * OO);
        *reinterpret_cast<float4*>(&sm.Bs[p][kk * OO + o4 * 4]) =
            *reinterpret_cast<const float4*>(src + o4 * 4);
    }
}

__global__ void __launch_bounds__(NTHREADS, 2)
btconv_kernel(const float* __restrict__ nodes,
              const int*   __restrict__ children,
              const float* __restrict__ w_t,
              const float* __restrict__ w_l,
              const float* __restrict__ w_r,
              const float* __restrict__ bias,
              float*       __restrict__ out)
{
    extern __shared__ char smem_raw[];
    Smem& sm = *reinterpret_cast<Smem*>(smem_raw);

    const int tid = threadIdx.x;
    const int gn0 = blockIdx.x * MT;          // flattened (b*N + n) start; 64 | 2048 so no batch straddle
    const int b   = gn0 / NN;
    const int n0  = gn0 - b * NN;
    const float* __restrict__ nodesB = nodes + (size_t)b * NN * FF;

    // ---------------- phase 1: coefficients + gather -> transposed X tile ----------------
    {
        const int m  = tid & (MT - 1);        // node within tile
        const int fg = tid >> 6;              // 0..1 -> 64-float feature half

        // per-thread coefficients (computed redundantly by the 2 threads sharing m)
        const int* chp = children + (size_t)(gn0 + m) * CC;
        int ch[CC];
        int ns = 0;
#pragma unroll
        for (int c = 0; c < CC; ++c) { ch[c] = chp[c]; ns += (ch[c] != 0); }
        const float nsf = (float)ns;

        float crv[CC], clv[CC];
#pragma unroll
        for (int c = 0; c < CC; ++c) {
            const float mfl = (ch[c] != 0) ? 1.0f : 0.0f;
            float cr;
            if (ns == 1) cr = (c == 0) ? 0.5f : 0.0f;
            else         cr = ((float)c * mfl) / (nsf - 1.0f);   // ns==0: 0/-1 = -0
            crv[c] = cr * mfl;                 // mask folded: masked child == node 0 row * 0
            clv[c] = (1.0f - cr) * mfl;
        }

        const float* __restrict__ xrow = nodesB + (size_t)(n0 + m) * FF;

#pragma unroll 4
        for (int q = 0; q < 16; ++q) {
            const int f = fg * 64 + q * 4;
            const float4 xt = *reinterpret_cast<const float4*>(xrow + f);
            float4 r = f4zero(), l = f4zero();
#pragma unroll
            for (int c = 0; c < CC; ++c) {
                const float4 v = *reinterpret_cast<const float4*>(nodesB + (size_t)ch[c] * FF + f);
                r.x += crv[c] * v.x; r.y += crv[c] * v.y;
                r.z += crv[c] * v.z; r.w += crv[c] * v.w;
                l.x += clv[c] * v.x; l.y += clv[c] * v.y;
                l.z += clv[c] * v.z; l.w += clv[c] * v.w;
            }
            float* A0 = &sm.As[(f        ) * MT + m];
            float* A1 = &sm.As[(FF   + f ) * MT + m];
            float* A2 = &sm.As[(2*FF + f ) * MT + m];
            A0[0*MT] = xt.x; A0[1*MT] = xt.y; A0[2*MT] = xt.z; A0[3*MT] = xt.w;
            A1[0*MT] = r.x;  A1[1*MT] = r.y;  A1[2*MT] = r.z;  A1[3*MT] = r.w;
            A2[0*MT] = l.x;  A2[1*MT] = l.y;  A2[2*MT] = l.z;  A2[3*MT] = l.w;
        }
    }

    // stage first W chunk (writes Bs only; no dependence on As)
    stage_w(sm, 0, 0, tid, w_t, w_r, w_l);
    __syncthreads();

    // ---------------- phase 2: GEMM  C[64][128] = As^T @ W ----------------
    const int tx = tid & 15;          // -> 8 output columns: tx*8 .. tx*8+7
    const int ty = tid >> 4;          // -> 8 output rows:    ty*8 .. ty*8+7

    float acc[8][8];
#pragma unroll
    for (int i = 0; i < 8; ++i)
#pragma unroll
        for (int j = 0; j < 8; ++j) acc[i][j] = 0.f;

    for (int c = 0; c < NCHUNK; ++c) {
        const int p = c & 1;
        if (c + 1 < NCHUNK) stage_w(sm, c + 1, p ^ 1, tid, w_t, w_r, w_l);

#pragma unroll
        for (int kk = 0; kk < KT; ++kk) {
            const int k = c * KT + kk;
            const float4 a0 = *reinterpret_cast<const float4*>(&sm.As[k * MT + ty * 8]);
            const float4 a1 = *reinterpret_cast<const float4*>(&sm.As[k * MT + ty * 8 + 4]);
            const float4 b0 = *reinterpret_cast<const float4*>(&sm.Bs[p][kk * OO + tx * 8]);
            const float4 b1 = *reinterpret_cast<const float4*>(&sm.Bs[p][kk * OO + tx * 8 + 4]);
            const float av[8] = {a0.x, a0.y, a0.z, a0.w, a1.x, a1.y, a1.z, a1.w};
            const float bv[8] = {b0.x, b0.y, b0.z, b0.w, b1.x, b1.y, b1.z, b1.w};
#pragma unroll
            for (int i = 0; i < 8; ++i)
#pragma unroll
                for (int j = 0; j < 8; ++j)
                    acc[i][j] += av[i] * bv[j];
        }
        __syncthreads();
    }

    // ---------------- epilogue: bias + relu + store ----------------
    const float4 bb0 = *reinterpret_cast<const float4*>(bias + tx * 8);
    const float4 bb1 = *reinterpret_cast<const float4*>(bias + tx * 8 + 4);
    const float bv[8] = {bb0.x, bb0.y, bb0.z, bb0.w, bb1.x, bb1.y, bb1.z, bb1.w};

#pragma unroll
    for (int i = 0; i < 8; ++i) {
        const int m = ty * 8 + i;
        float* row = out + (size_t)(gn0 + m) * OO + tx * 8;
        float4 o0, o1;
        o0.x = fmaxf(acc[i][0] + bv[0], 0.f);
        o0.y = fmaxf(acc[i][1] + bv[1], 0.f);
        o0.z = fmaxf(acc[i][2] + bv[2], 0.f);
        o0.w = fmaxf(acc[i][3] + bv[3], 0.f);
        o1.x = fmaxf(acc[i][4] + bv[4], 0.f);
        o1.y = fmaxf(acc[i][5] + bv[5], 0.f);
        o1.z = fmaxf(acc[i][6] + bv[6], 0.f);
        o1.w = fmaxf(acc[i][7] + bv[7], 0.f);
        *reinterpret_cast<float4*>(row)     = o0;
        *reinterpret_cast<float4*>(row + 4) = o1;
    }
}

extern "C" void kernel_launch(void* const* d_in, const int* in_sizes, int n_in,
                              void* d_out, int out_size) {
    const float* nodes    = (const float*)d_in[0];   // [B,N,F]
    const int*   children = (const int*)  d_in[1];   // [B,N,C]
    const float* w_t      = (const float*)d_in[2];   // [F,O]
    const float* w_l      = (const float*)d_in[3];   // [F,O]
    const float* w_r      = (const float*)d_in[4];   // [F,O]
    const float* bias     = (const float*)d_in[5];   // [O]
    float* out = (float*)d_out;                      // [B,N,O]

    const int smem = (int)sizeof(Smem);              // 112 KB
    cudaFuncSetAttribute(btconv_kernel, cudaFuncAttributeMaxDynamicSharedMemorySize, smem);

    const int grid = (BATCH * NN) / MT;              // 1024 blocks
    btconv_kernel<<<grid, NTHREADS, smem>>>(nodes, children, w_t, w_l, w_r, bias, out);
}

// round 4
// speedup vs baseline: 2.5394x; 2.5394x over previous
#include <cuda_runtime.h>
#include <cuda_bf16.h>
#include <cstdint>

#define BATCH 32
#define NN    2048
#define CC    8
#define FF    128
#define OO    128
#define MT    128
#define NTHREADS 256

// ---- smem layout (bytes): A(hi,lo) | AL(hi,lo) | B(hi,lo) ----
#define A_HI   0
#define A_LO   32768
#define AL_HI  65536
#define AL_LO  98304
#define B_HI   131072
#define B_LO   163840
#define SM_TOTAL 196608

// Pre-swizzled W images: [term(t,r,l)][hi/lo][128 n-rows x 128 k-cols bf16]
__device__ __align__(16) unsigned char g_wimg[3][2][128 * 128 * 2];

// swizzled byte offset of element (row, k) in a [row][k0..127] bf16 tile with 256B rows
__device__ __host__ __forceinline__ uint32_t tile_off(int row, int k) {
    return (uint32_t)(row * 256 + ((((k >> 3) & 15) ^ (row & 7)) << 4) + (k & 7) * 2);
}

__device__ __forceinline__ uint32_t smem_u32(const void* p) {
    uint32_t a;
    asm("{ .reg .u64 t; cvta.to.shared.u64 t, %1; cvt.u32.u64 %0, t; }" : "=r"(a) : "l"(p));
    return a;
}
__device__ __forceinline__ void ldsm4(uint32_t* r, uint32_t addr) {
    asm volatile("ldmatrix.sync.aligned.m8n8.x4.shared.b16 {%0,%1,%2,%3}, [%4];"
        : "=r"(r[0]), "=r"(r[1]), "=r"(r[2]), "=r"(r[3]) : "r"(addr));
}
__device__ __forceinline__ void mma16816(float* d, const uint32_t* a, const uint32_t* b) {
    asm volatile("mma.sync.aligned.m16n8k16.row.col.f32.bf16.bf16.f32 "
        "{%0,%1,%2,%3}, {%4,%5,%6,%7}, {%8,%9}, {%0,%1,%2,%3};"
        : "+f"(d[0]), "+f"(d[1]), "+f"(d[2]), "+f"(d[3])
        : "r"(a[0]), "r"(a[1]), "r"(a[2]), "r"(a[3]), "r"(b[0]), "r"(b[1]));
}
__device__ __forceinline__ uint32_t pack_bf2(__nv_bfloat16 a, __nv_bfloat16 b) {
    __nv_bfloat162 t = __halves2bfloat162(a, b);
    return *reinterpret_cast<uint32_t*>(&t);
}
// split float4 -> hi/lo bf16, store 8B each at (m, k=k4*4) of tiles at smem+hi_base/lo_base
__device__ __forceinline__ void store_hilo(char* smem, int hi_base, int lo_base,
                                           int m, int k4, float4 v) {
    const uint32_t off = tile_off(m, k4 * 4);
    const __nv_bfloat16 hx = __float2bfloat16(v.x), hy = __float2bfloat16(v.y);
    const __nv_bfloat16 hz = __float2bfloat16(v.z), hw = __float2bfloat16(v.w);
    uint2 hi;
    hi.x = pack_bf2(hx, hy); hi.y = pack_bf2(hz, hw);
    uint2 lo;
    lo.x = pack_bf2(__float2bfloat16(v.x - __bfloat162float(hx)),
                    __float2bfloat16(v.y - __bfloat162float(hy)));
    lo.y = pack_bf2(__float2bfloat16(v.z - __bfloat162float(hz)),
                    __float2bfloat16(v.w - __bfloat162float(hw)));
    *reinterpret_cast<uint2*>(smem + hi_base + off) = hi;
    *reinterpret_cast<uint2*>(smem + lo_base + off) = lo;
}

// ---------------- prep: W -> swizzled bf16 hi/lo images (B stored [n][k]) ----------------
__global__ void prep_w(const float* __restrict__ w_t,
                       const float* __restrict__ w_l,
                       const float* __restrict__ w_r)
{
    const int term = blockIdx.x;                       // 0=t 1=r 2=l
    const float* src = (term == 0) ? w_t : (term == 1) ? w_r : w_l;
    for (int idx = threadIdx.x; idx < 128 * 128; idx += blockDim.x) {
        const int n = idx >> 7, k = idx & 127;
        const float v = src[(size_t)k * OO + n];       // B[n][k] = W[k][n]
        const __nv_bfloat16 h = __float2bfloat16(v);
        const __nv_bfloat16 l = __float2bfloat16(v - __bfloat162float(h));
        const uint32_t off = tile_off(n, k);
        *reinterpret_cast<__nv_bfloat16*>(&g_wimg[term][0][off]) = h;
        *reinterpret_cast<__nv_bfloat16*>(&g_wimg[term][1][off]) = l;
    }
}

// ---------------- main kernel ----------------
__device__ __forceinline__ void copy_b(char* smem, int tid, int term) {
#pragma unroll
    for (int i = 0; i < 16; ++i) {
        const int idx  = tid + i * NTHREADS;    // 0..4095 uint4
        const int prec = idx >> 11;             // 0=hi 1=lo
        const int q    = idx & 2047;
        const uint4 v = *reinterpret_cast<const uint4*>(&g_wimg[term][prec][q * 16]);
        *reinterpret_cast<uint4*>(smem + (prec ? B_LO : B_HI) + q * 16) = v;
    }
}

__device__ __forceinline__ void gemm_phase(uint32_t sb, int a_hi, int a_lo,
                                           int warp_m, int warp_n, int lane,
                                           float acc[2][8][4])
{
    uint32_t a_base[2], b_base[4];
    uint32_t a_sx[2], b_sx[4];
#pragma unroll
    for (int mt = 0; mt < 2; ++mt) {
        const int m = warp_m + mt * 16 + (lane & 15);
        a_base[mt] = (uint32_t)(m * 256);
        a_sx[mt]   = (uint32_t)(m & 7);
    }
#pragma unroll
    for (int np = 0; np < 4; ++np) {
        const int n = warp_n + np * 16 + (lane & 7) + ((lane >> 4) << 3);
        b_base[np] = (uint32_t)(n * 256);
        b_sx[np]   = (uint32_t)(n & 7);
    }
    const uint32_t a_cadd = (uint32_t)(lane >> 4);
    const uint32_t b_cadd = (uint32_t)((lane >> 3) & 1);

#pragma unroll
    for (int ks = 0; ks < 8; ++ks) {
        uint32_t ahi[2][4], alo[2][4];
#pragma unroll
        for (int mt = 0; mt < 2; ++mt) {
            const uint32_t coff = a_base[mt] + ((((uint32_t)(ks * 2) + a_cadd) ^ a_sx[mt]) << 4);
            ldsm4(ahi[mt], sb + a_hi + coff);
            ldsm4(alo[mt], sb + a_lo + coff);
        }
#pragma unroll
        for (int np = 0; np < 4; ++np) {
            const uint32_t coff = b_base[np] + ((((uint32_t)(ks * 2) + b_cadd) ^ b_sx[np]) << 4);
            uint32_t bhi[4], blo[4];
            ldsm4(bhi, sb + B_HI + coff);
            ldsm4(blo, sb + B_LO + coff);
#pragma unroll
            for (int mt = 0; mt < 2; ++mt) {
#pragma unroll
                for (int ns = 0; ns < 2; ++ns) {
                    float* d = acc[mt][np * 2 + ns];
                    mma16816(d, ahi[mt], bhi + ns * 2);
                    mma16816(d, alo[mt], bhi + ns * 2);
                    mma16816(d, ahi[mt], blo + ns * 2);
                }
            }
        }
    }
}

__global__ void __launch_bounds__(NTHREADS, 1)
btconv_mma_kernel(const float* __restrict__ nodes,
                  const int*   __restrict__ children,
                  const float* __restrict__ bias,
                  float*       __restrict__ out)
{
    extern __shared__ char smem[];
    const uint32_t sb = smem_u32(smem);
    const int tid  = threadIdx.x;
    const int wid  = tid >> 5;
    const int lane = tid & 31;

    const int gn0 = blockIdx.x * MT;
    const int b   = gn0 / NN;
    const int n0  = gn0 - b * NN;
    const float* __restrict__ nodesB = nodes + (size_t)b * NN * FF;

    const int warp_m = (wid & 3) * 32;
    const int warp_n = (wid >> 2) * 64;

    float acc[2][8][4];
#pragma unroll
    for (int i = 0; i < 2; ++i)
#pragma unroll
        for (int j = 0; j < 8; ++j)
#pragma unroll
            for (int q = 0; q < 4; ++q) acc[i][j][q] = 0.f;

    // ---------- phase t: A = x rows ----------
    copy_b(smem, tid, 0);
#pragma unroll 2
    for (int p = 0; p < 16; ++p) {
        const int m = wid * 16 + p;
        const float4 v = *reinterpret_cast<const float4*>(
            nodesB + (size_t)(n0 + m) * FF + lane * 4);
        store_hilo(smem, A_HI, A_LO, m, lane, v);
    }
    __syncthreads();
    gemm_phase(sb, A_HI, A_LO, warp_m, warp_n, lane, acc);
    __syncthreads();

    // ---------- gather: A <- agg_r, AL <- agg_l ; stage B_r ----------
    copy_b(smem, tid, 1);
#pragma unroll 2
    for (int p = 0; p < 16; ++p) {
        const int m = wid * 16 + p;
        const int* chp = children + (size_t)(gn0 + m) * CC;
        int ch[CC];
        int ns = 0;
#pragma unroll
        for (int c = 0; c < CC; ++c) { ch[c] = chp[c]; ns += (ch[c] != 0); }
        const float nsf = (float)ns;
        float crv[CC], clv[CC];
#pragma unroll
        for (int c = 0; c < CC; ++c) {
            const float mfl = (ch[c] != 0) ? 1.0f : 0.0f;
            float cr;
            if (ns == 1) cr = (c == 0) ? 0.5f : 0.0f;
            else         cr = ((float)c * mfl) / (nsf - 1.0f);   // ns==0: 0/-1 = -0
            crv[c] = cr * mfl;
            clv[c] = (1.0f - cr) * mfl;
        }
        float4 r; r.x = r.y = r.z = r.w = 0.f;
        float4 l; l.x = l.y = l.z = l.w = 0.f;
        const float* base = nodesB + lane * 4;
#pragma unroll
        for (int c = 0; c < CC; ++c) {
            const float4 v = *reinterpret_cast<const float4*>(base + (size_t)ch[c] * FF);
            r.x += crv[c] * v.x; r.y += crv[c] * v.y; r.z += crv[c] * v.z; r.w += crv[c] * v.w;
            l.x += clv[c] * v.x; l.y += clv[c] * v.y; l.z += clv[c] * v.z; l.w += clv[c] * v.w;
        }
        store_hilo(smem, A_HI,  A_LO,  m, lane, r);
        store_hilo(smem, AL_HI, AL_LO, m, lane, l);
    }
    __syncthreads();
    gemm_phase(sb, A_HI, A_LO, warp_m, warp_n, lane, acc);
    __syncthreads();

    // ---------- phase l: B_l, A = AL ----------
    copy_b(smem, tid, 2);
    __syncthreads();
    gemm_phase(sb, AL_HI, AL_LO, warp_m, warp_n, lane, acc);

    // ---------- epilogue: bias + relu + store ----------
#pragma unroll
    for (int mt = 0; mt < 2; ++mt) {
#pragma unroll
        for (int i = 0; i < 2; ++i) {
            const int m = gn0 + warp_m + mt * 16 + (lane >> 2) + i * 8;
            float* orow = out + (size_t)m * OO;
#pragma unroll
            for (int nt = 0; nt < 8; ++nt) {
                const int n = warp_n + nt * 8 + (lane & 3) * 2;
                float2 o;
                o.x = fmaxf(acc[mt][nt][i * 2 + 0] + __ldg(bias + n),     0.f);
                o.y = fmaxf(acc[mt][nt][i * 2 + 1] + __ldg(bias + n + 1), 0.f);
                *reinterpret_cast<float2*>(orow + n) = o;
            }
        }
    }
}

extern "C" void kernel_launch(void* const* d_in, const int* in_sizes, int n_in,
                              void* d_out, int out_size) {
    const float* nodes    = (const float*)d_in[0];   // [B,N,F]
    const int*   children = (const int*)  d_in[1];   // [B,N,C]
    const float* w_t      = (const float*)d_in[2];   // [F,O]
    const float* w_l      = (const float*)d_in[3];   // [F,O]
    const float* w_r      = (const float*)d_in[4];   // [F,O]
    const float* bias     = (const float*)d_in[5];   // [O]
    float* out = (float*)d_out;                      // [B,N,O]

    prep_w<<<3, 256>>>(w_t, w_l, w_r);

    cudaFuncSetAttribute(btconv_mma_kernel, cudaFuncAttributeMaxDynamicSharedMemorySize, SM_TOTAL);
    const int grid = (BATCH * NN) / MT;              // 512 blocks
    btconv_mma_kernel<<<grid, NTHREADS, SM_TOTAL>>>(nodes, children, bias, out);
}

// round 5
// speedup vs baseline: 3.7011x; 1.4575x over previous
#include <cuda_runtime.h>
#include <cuda_bf16.h>
#include <cstdint>

#define BATCH 32
#define NN    2048
#define CC    8
#define FF    128
#define OO    128
#define MT    128
#define NTHREADS 512

// ---- smem layout (bytes): A(hi,lo) | AL(hi,lo) | B(hi,lo) ----
#define A_HI   0
#define A_LO   32768
#define AL_HI  65536
#define AL_LO  98304
#define B_HI   131072
#define B_LO   163840
#define SM_TOTAL 196608

// Pre-swizzled W images: [term(t,r,l)][hi/lo][128 n-rows x 128 k-cols bf16]
__device__ __align__(16) unsigned char g_wimg[3][2][128 * 128 * 2];

// swizzled byte offset of element (row, k) in a [row][k0..127] bf16 tile with 256B rows
__device__ __host__ __forceinline__ uint32_t tile_off(int row, int k) {
    return (uint32_t)(row * 256 + ((((k >> 3) & 15) ^ (row & 7)) << 4) + (k & 7) * 2);
}

__device__ __forceinline__ uint32_t smem_u32(const void* p) {
    uint32_t a;
    asm("{ .reg .u64 t; cvta.to.shared.u64 t, %1; cvt.u32.u64 %0, t; }" : "=r"(a) : "l"(p));
    return a;
}
__device__ __forceinline__ void ldsm4(uint32_t* r, uint32_t addr) {
    asm volatile("ldmatrix.sync.aligned.m8n8.x4.shared.b16 {%0,%1,%2,%3}, [%4];"
        : "=r"(r[0]), "=r"(r[1]), "=r"(r[2]), "=r"(r[3]) : "r"(addr));
}
__device__ __forceinline__ void mma16816(float* d, const uint32_t* a, const uint32_t* b) {
    asm volatile("mma.sync.aligned.m16n8k16.row.col.f32.bf16.bf16.f32 "
        "{%0,%1,%2,%3}, {%4,%5,%6,%7}, {%8,%9}, {%0,%1,%2,%3};"
        : "+f"(d[0]), "+f"(d[1]), "+f"(d[2]), "+f"(d[3])
        : "r"(a[0]), "r"(a[1]), "r"(a[2]), "r"(a[3]), "r"(b[0]), "r"(b[1]));
}
__device__ __forceinline__ uint32_t pack_bf2(__nv_bfloat16 a, __nv_bfloat16 b) {
    __nv_bfloat162 t = __halves2bfloat162(a, b);
    return *reinterpret_cast<uint32_t*>(&t);
}
__device__ __forceinline__ void store_hilo(char* smem, int hi_base, int lo_base,
                                           int m, int k4, float4 v) {
    const uint32_t off = tile_off(m, k4 * 4);
    const __nv_bfloat16 hx = __float2bfloat16(v.x), hy = __float2bfloat16(v.y);
    const __nv_bfloat16 hz = __float2bfloat16(v.z), hw = __float2bfloat16(v.w);
    uint2 hi;
    hi.x = pack_bf2(hx, hy); hi.y = pack_bf2(hz, hw);
    uint2 lo;
    lo.x = pack_bf2(__float2bfloat16(v.x - __bfloat162float(hx)),
                    __float2bfloat16(v.y - __bfloat162float(hy)));
    lo.y = pack_bf2(__float2bfloat16(v.z - __bfloat162float(hz)),
                    __float2bfloat16(v.w - __bfloat162float(hw)));
    *reinterpret_cast<uint2*>(smem + hi_base + off) = hi;
    *reinterpret_cast<uint2*>(smem + lo_base + off) = lo;
}

// ---------------- prep: W -> swizzled bf16 hi/lo images (B stored [n][k]) ----------------
__global__ void prep_w(const float* __restrict__ w_t,
                       const float* __restrict__ w_l,
                       const float* __restrict__ w_r)
{
    const int term = blockIdx.x;                       // 0=t 1=r 2=l
    const float* src = (term == 0) ? w_t : (term == 1) ? w_r : w_l;
    for (int idx = threadIdx.x; idx < 128 * 128; idx += blockDim.x) {
        const int n = idx >> 7, k = idx & 127;
        const float v = src[(size_t)k * OO + n];       // B[n][k] = W[k][n]
        const __nv_bfloat16 h = __float2bfloat16(v);
        const __nv_bfloat16 l = __float2bfloat16(v - __bfloat162float(h));
        const uint32_t off = tile_off(n, k);
        *reinterpret_cast<__nv_bfloat16*>(&g_wimg[term][0][off]) = h;
        *reinterpret_cast<__nv_bfloat16*>(&g_wimg[term][1][off]) = l;
    }
}

// ---------------- main kernel ----------------
__device__ __forceinline__ void copy_b_async(char* smem, int tid, int term) {
#pragma unroll
    for (int i = 0; i < 8; ++i) {
        const int idx  = tid + i * NTHREADS;    // 0..4095 uint4
        const int prec = idx >> 11;             // 0=hi 1=lo
        const int q    = idx & 2047;
        const uint32_t dst = smem_u32(smem + (prec ? B_LO : B_HI) + q * 16);
        const void* src = &g_wimg[term][prec][q * 16];
        asm volatile("cp.async.cg.shared.global [%0], [%1], 16;" :: "r"(dst), "l"(src) : "memory");
    }
    asm volatile("cp.async.commit_group;" ::: "memory");
}
#define CPASYNC_WAIT() asm volatile("cp.async.wait_group 0;" ::: "memory")

// warp tile: 32m x 32n.  acc[mt 2][n8 4][4]
__device__ __forceinline__ void gemm_phase(uint32_t sb, int a_hi, int a_lo,
                                           int warp_m, int warp_n, int lane,
                                           float acc[2][4][4])
{
    uint32_t a_base[2], a_sx[2], b_base[2], b_sx[2];
#pragma unroll
    for (int mt = 0; mt < 2; ++mt) {
        const int m = warp_m + mt * 16 + (lane & 15);
        a_base[mt] = (uint32_t)(m * 256);
        a_sx[mt]   = (uint32_t)(m & 7);
    }
#pragma unroll
    for (int np = 0; np < 2; ++np) {
        const int n = warp_n + np * 16 + (lane & 7) + ((lane >> 4) << 3);
        b_base[np] = (uint32_t)(n * 256);
        b_sx[np]   = (uint32_t)(n & 7);
    }
    const uint32_t a_cadd = (uint32_t)(lane >> 4);
    const uint32_t b_cadd = (uint32_t)((lane >> 3) & 1);

#pragma unroll
    for (int ks = 0; ks < 8; ++ks) {
        uint32_t ahi[2][4], alo[2][4];
#pragma unroll
        for (int mt = 0; mt < 2; ++mt) {
            const uint32_t coff = a_base[mt] + ((((uint32_t)(ks * 2) + a_cadd) ^ a_sx[mt]) << 4);
            ldsm4(ahi[mt], sb + a_hi + coff);
            ldsm4(alo[mt], sb + a_lo + coff);
        }
#pragma unroll
        for (int np = 0; np < 2; ++np) {
            const uint32_t coff = b_base[np] + ((((uint32_t)(ks * 2) + b_cadd) ^ b_sx[np]) << 4);
            uint32_t bhi[4], blo[4];
            ldsm4(bhi, sb + B_HI + coff);
            ldsm4(blo, sb + B_LO + coff);
#pragma unroll
            for (int mt = 0; mt < 2; ++mt) {
#pragma unroll
                for (int ns = 0; ns < 2; ++ns) {
                    float* d = acc[mt][np * 2 + ns];
                    mma16816(d, ahi[mt], bhi + ns * 2);
                    mma16816(d, alo[mt], bhi + ns * 2);
                    mma16816(d, ahi[mt], blo + ns * 2);
                }
            }
        }
    }
}

__global__ void __launch_bounds__(NTHREADS, 1)
btconv_mma_kernel(const float* __restrict__ nodes,
                  const int*   __restrict__ children,
                  const float* __restrict__ bias,
                  float*       __restrict__ out)
{
    extern __shared__ char smem[];
    const uint32_t sb = smem_u32(smem);
    const int tid  = threadIdx.x;
    const int wid  = tid >> 5;       // 0..15
    const int lane = tid & 31;

    const int gn0 = blockIdx.x * MT;
    const int b   = gn0 / NN;
    const int n0  = gn0 - b * NN;
    const float* __restrict__ nodesB = nodes + (size_t)b * NN * FF;

    const int warp_m = (wid & 3) * 32;
    const int warp_n = (wid >> 2) * 32;

    float acc[2][4][4];
#pragma unroll
    for (int i = 0; i < 2; ++i)
#pragma unroll
        for (int j = 0; j < 4; ++j)
#pragma unroll
            for (int q = 0; q < 4; ++q) acc[i][j][q] = 0.f;

    // ---------- phase t: B_t async + A = x rows ----------
    copy_b_async(smem, tid, 0);
#pragma unroll 2
    for (int p = 0; p < 8; ++p) {
        const int m = wid * 8 + p;
        const float4 v = *reinterpret_cast<const float4*>(
            nodesB + (size_t)(n0 + m) * FF + lane * 4);
        store_hilo(smem, A_HI, A_LO, m, lane, v);
    }
    CPASYNC_WAIT();
    __syncthreads();
    gemm_phase(sb, A_HI, A_LO, warp_m, warp_n, lane, acc);
    __syncthreads();

    // ---------- gather: B_r async + A <- agg_r, AL <- agg_l ----------
    copy_b_async(smem, tid, 1);
#pragma unroll 2
    for (int p = 0; p < 8; ++p) {
        const int m = wid * 8 + p;
        const int* chp = children + (size_t)(gn0 + m) * CC;
        int ch[CC];
        int ns = 0;
#pragma unroll
        for (int c = 0; c < CC; ++c) { ch[c] = chp[c]; ns += (ch[c] != 0); }
        const float nsf = (float)ns;
        const float rdenom = (ns > 1) ? __frcp_rn(nsf - 1.0f) : 0.0f;
        float crv[CC], clv[CC];
#pragma unroll
        for (int c = 0; c < CC; ++c) {
            const float mfl = (ch[c] != 0) ? 1.0f : 0.0f;
            float cr;
            if (ns == 1) cr = (c == 0) ? 0.5f : 0.0f;
            else         cr = (float)c * mfl * rdenom;
            crv[c] = cr * mfl;
            clv[c] = (1.0f - cr) * mfl;
        }
        float4 r; r.x = r.y = r.z = r.w = 0.f;
        float4 l; l.x = l.y = l.z = l.w = 0.f;
        const float* base = nodesB + lane * 4;
#pragma unroll
        for (int c = 0; c < CC; ++c) {
            const float4 v = *reinterpret_cast<const float4*>(base + (size_t)ch[c] * FF);
            r.x += crv[c] * v.x; r.y += crv[c] * v.y; r.z += crv[c] * v.z; r.w += crv[c] * v.w;
            l.x += clv[c] * v.x; l.y += clv[c] * v.y; l.z += clv[c] * v.z; l.w += clv[c] * v.w;
        }
        store_hilo(smem, A_HI,  A_LO,  m, lane, r);
        store_hilo(smem, AL_HI, AL_LO, m, lane, l);
    }
    CPASYNC_WAIT();
    __syncthreads();
    gemm_phase(sb, A_HI, A_LO, warp_m, warp_n, lane, acc);
    __syncthreads();

    // ---------- phase l: B_l async, A = AL ----------
    copy_b_async(smem, tid, 2);
    CPASYNC_WAIT();
    __syncthreads();
    gemm_phase(sb, AL_HI, AL_LO, warp_m, warp_n, lane, acc);

    // ---------- epilogue: bias + relu + store ----------
#pragma unroll
    for (int mt = 0; mt < 2; ++mt) {
#pragma unroll
        for (int i = 0; i < 2; ++i) {
            const int m = gn0 + warp_m + mt * 16 + (lane >> 2) + i * 8;
            float* orow = out + (size_t)m * OO;
#pragma unroll
            for (int nt = 0; nt < 4; ++nt) {
                const int n = warp_n + nt * 8 + (lane & 3) * 2;
                float2 o;
                o.x = fmaxf(acc[mt][nt][i * 2 + 0] + __ldg(bias + n),     0.f);
                o.y = fmaxf(acc[mt][nt][i * 2 + 1] + __ldg(bias + n + 1), 0.f);
                *reinterpret_cast<float2*>(orow + n) = o;
            }
        }
    }
}

extern "C" void kernel_launch(void* const* d_in, const int* in_sizes, int n_in,
                              void* d_out, int out_size) {
    const float* nodes    = (const float*)d_in[0];   // [B,N,F]
    const int*   children = (const int*)  d_in[1];   // [B,N,C]
    const float* w_t      = (const float*)d_in[2];   // [F,O]
    const float* w_l      = (const float*)d_in[3];   // [F,O]
    const float* w_r      = (const float*)d_in[4];   // [F,O]
    const float* bias     = (const float*)d_in[5];   // [O]
    float* out = (float*)d_out;                      // [B,N,O]

    prep_w<<<3, 256>>>(w_t, w_l, w_r);

    cudaFuncSetAttribute(btconv_mma_kernel, cudaFuncAttributeMaxDynamicSharedMemorySize, SM_TOTAL);
    const int grid = (BATCH * NN) / MT;              // 512 blocks
    btconv_mma_kernel<<<grid, NTHREADS, SM_TOTAL>>>(nodes, children, bias, out);
}

// round 6
// speedup vs baseline: 4.7478x; 1.2828x over previous
#include <cuda_runtime.h>
#include <cuda_fp16.h>
#include <cstdint>

#define BATCH 32
#define NN    2048
#define CC    8
#define FF    128
#define OO    128
#define MT    128
#define NTHREADS 512

// ---- smem layout (bytes) ----
// Three A tiles (fp16, 128 rows x 128 k = 32KB each), two B buffers (hi+lo, 64KB each)
#define A_T   0
#define A_R   32768
#define A_L   65536
#define B0    98304          // hi at +0, lo at +32768
#define B1    163840
#define SM_TOTAL 229376      // 224 KB

// Pre-split W images: [term(t,r,l)][hi/lo][128 n-rows x 128 k-cols fp16, swizzled]
__device__ __align__(16) unsigned char g_wimg[3][2][128 * 128 * 2];

// swizzled byte offset of element (row, k) in a [row][k] fp16 tile with 256B rows
__device__ __host__ __forceinline__ uint32_t tile_off(int row, int k) {
    return (uint32_t)(row * 256 + ((((k >> 3) & 15) ^ (row & 7)) << 4) + (k & 7) * 2);
}

__device__ __forceinline__ uint32_t smem_u32(const void* p) {
    uint32_t a;
    asm("{ .reg .u64 t; cvta.to.shared.u64 t, %1; cvt.u32.u64 %0, t; }" : "=r"(a) : "l"(p));
    return a;
}
__device__ __forceinline__ void ldsm4(uint32_t* r, uint32_t addr) {
    asm volatile("ldmatrix.sync.aligned.m8n8.x4.shared.b16 {%0,%1,%2,%3}, [%4];"
        : "=r"(r[0]), "=r"(r[1]), "=r"(r[2]), "=r"(r[3]) : "r"(addr));
}
__device__ __forceinline__ void mma16816(float* d, const uint32_t* a, const uint32_t* b) {
    asm volatile("mma.sync.aligned.m16n8k16.row.col.f32.f16.f16.f32 "
        "{%0,%1,%2,%3}, {%4,%5,%6,%7}, {%8,%9}, {%0,%1,%2,%3};"
        : "+f"(d[0]), "+f"(d[1]), "+f"(d[2]), "+f"(d[3])
        : "r"(a[0]), "r"(a[1]), "r"(a[2]), "r"(a[3]), "r"(b[0]), "r"(b[1]));
}
// store float4 as 4 fp16 (8B) at (m, k4*4) of tile at smem+base
__device__ __forceinline__ void store_h4(char* smem, int base, int m, int k4, float4 v) {
    const uint32_t off = tile_off(m, k4 * 4);
    __half2 h0 = __halves2half2(__float2half_rn(v.x), __float2half_rn(v.y));
    __half2 h1 = __halves2half2(__float2half_rn(v.z), __float2half_rn(v.w));
    uint2 u;
    u.x = *reinterpret_cast<uint32_t*>(&h0);
    u.y = *reinterpret_cast<uint32_t*>(&h1);
    *reinterpret_cast<uint2*>(smem + base + off) = u;
}

// ---------------- prep: W -> swizzled fp16 hi/lo images (B stored [n][k]) ----------------
__global__ void prep_w(const float* __restrict__ w_t,
                       const float* __restrict__ w_l,
                       const float* __restrict__ w_r)
{
    const int term = blockIdx.x;                       // 0=t 1=r 2=l
    const float* src = (term == 0) ? w_t : (term == 1) ? w_r : w_l;
    for (int idx = threadIdx.x; idx < 128 * 128; idx += blockDim.x) {
        const int n = idx >> 7, k = idx & 127;
        const float v = src[(size_t)k * OO + n];       // B[n][k] = W[k][n]
        const __half h = __float2half_rn(v);
        const __half l = __float2half_rn(v - __half2float(h));
        const uint32_t off = tile_off(n, k);
        *reinterpret_cast<__half*>(&g_wimg[term][0][off]) = h;
        *reinterpret_cast<__half*>(&g_wimg[term][1][off]) = l;
    }
}

// ---------------- main kernel ----------------
__device__ __forceinline__ void copy_b_async(char* smem, int tid, int term, int dst) {
#pragma unroll
    for (int i = 0; i < 8; ++i) {
        const int idx  = tid + i * NTHREADS;    // 0..4095 uint4
        const int prec = idx >> 11;             // 0=hi 1=lo
        const int q    = idx & 2047;
        const uint32_t d = smem_u32(smem + dst + prec * 32768 + q * 16);
        const void* src = &g_wimg[term][prec][q * 16];
        asm volatile("cp.async.cg.shared.global [%0], [%1], 16;" :: "r"(d), "l"(src) : "memory");
    }
    asm volatile("cp.async.commit_group;" ::: "memory");
}
#define CPASYNC_WAIT() asm volatile("cp.async.wait_group 0;" ::: "memory")

// warp tile: 32m x 32n; A single-prec fp16, B hi+lo -> 2 MMA passes
__device__ __forceinline__ void gemm_phase(uint32_t sb, int a_base_off, int b_buf,
                                           int warp_m, int warp_n, int lane,
                                           float acc[2][4][4])
{
    uint32_t a_base[2], a_sx[2], b_base[2], b_sx[2];
#pragma unroll
    for (int mt = 0; mt < 2; ++mt) {
        const int m = warp_m + mt * 16 + (lane & 15);
        a_base[mt] = (uint32_t)(m * 256);
        a_sx[mt]   = (uint32_t)(m & 7);
    }
#pragma unroll
    for (int np = 0; np < 2; ++np) {
        const int n = warp_n + np * 16 + (lane & 7) + ((lane >> 4) << 3);
        b_base[np] = (uint32_t)(n * 256);
        b_sx[np]   = (uint32_t)(n & 7);
    }
    const uint32_t a_cadd = (uint32_t)(lane >> 4);
    const uint32_t b_cadd = (uint32_t)((lane >> 3) & 1);
    const uint32_t bhi = sb + b_buf;
    const uint32_t blo = sb + b_buf + 32768;

#pragma unroll
    for (int ks = 0; ks < 8; ++ks) {
        uint32_t af[2][4], bh[2][4], bl[2][4];
#pragma unroll
        for (int mt = 0; mt < 2; ++mt) {
            const uint32_t coff = a_base[mt] + ((((uint32_t)(ks * 2) + a_cadd) ^ a_sx[mt]) << 4);
            ldsm4(af[mt], sb + a_base_off + coff);
        }
#pragma unroll
        for (int np = 0; np < 2; ++np) {
            const uint32_t coff = b_base[np] + ((((uint32_t)(ks * 2) + b_cadd) ^ b_sx[np]) << 4);
            ldsm4(bh[np], bhi + coff);
            ldsm4(bl[np], blo + coff);
        }
#pragma unroll
        for (int mt = 0; mt < 2; ++mt)
#pragma unroll
            for (int np = 0; np < 2; ++np)
#pragma unroll
                for (int ns = 0; ns < 2; ++ns) {
                    float* d = acc[mt][np * 2 + ns];
                    mma16816(d, af[mt], bh[np] + ns * 2);
                    mma16816(d, af[mt], bl[np] + ns * 2);
                }
    }
}

__global__ void __launch_bounds__(NTHREADS, 1)
btconv_mma_kernel(const float* __restrict__ nodes,
                  const int*   __restrict__ children,
                  const float* __restrict__ bias,
                  float*       __restrict__ out)
{
    extern __shared__ char smem[];
    const uint32_t sb = smem_u32(smem);
    const int tid  = threadIdx.x;
    const int wid  = tid >> 5;       // 0..15
    const int lane = tid & 31;

    const int gn0 = blockIdx.x * MT;
    const int b   = gn0 / NN;
    const int n0  = gn0 - b * NN;
    const float* __restrict__ nodesB = nodes + (size_t)b * NN * FF;

    const int warp_m = (wid & 3) * 32;
    const int warp_n = (wid >> 2) * 32;

    float acc[2][4][4];
#pragma unroll
    for (int i = 0; i < 2; ++i)
#pragma unroll
        for (int j = 0; j < 4; ++j)
#pragma unroll
            for (int q = 0; q < 4; ++q) acc[i][j][q] = 0.f;

    // ---------- stage B_t into B0 (async, overlaps the build phase) ----------
    copy_b_async(smem, tid, 0, B0);

    // ---------- single memory phase: build A_t, A_r, A_l ----------
#pragma unroll 2
    for (int p = 0; p < 8; ++p) {
        const int m = wid * 8 + p;
        // x row -> A_t
        const float4 xv = *reinterpret_cast<const float4*>(
            nodesB + (size_t)(n0 + m) * FF + lane * 4);
        store_h4(smem, A_T, m, lane, xv);

        // children gather -> A_r, A_l
        const int* chp = children + (size_t)(gn0 + m) * CC;
        int ch[CC];
        int ns = 0;
#pragma unroll
        for (int c = 0; c < CC; ++c) { ch[c] = chp[c]; ns += (ch[c] != 0); }
        const float rdenom = (ns > 1) ? __frcp_rn((float)ns - 1.0f) : 0.0f;
        float crv[CC], clv[CC];
#pragma unroll
        for (int c = 0; c < CC; ++c) {
            const float mfl = (ch[c] != 0) ? 1.0f : 0.0f;
            float cr;
            if (ns == 1) cr = (c == 0) ? 0.5f : 0.0f;
            else         cr = (float)c * mfl * rdenom;
            crv[c] = cr * mfl;
            clv[c] = (1.0f - cr) * mfl;
        }
        float4 r; r.x = r.y = r.z = r.w = 0.f;
        float4 l; l.x = l.y = l.z = l.w = 0.f;
        const float* base = nodesB + lane * 4;
#pragma unroll
        for (int c = 0; c < CC; ++c) {
            const float4 v = *reinterpret_cast<const float4*>(base + (size_t)ch[c] * FF);
            r.x += crv[c] * v.x; r.y += crv[c] * v.y; r.z += crv[c] * v.z; r.w += crv[c] * v.w;
            l.x += clv[c] * v.x; l.y += clv[c] * v.y; l.z += clv[c] * v.z; l.w += clv[c] * v.w;
        }
        store_h4(smem, A_R, m, lane, r);
        store_h4(smem, A_L, m, lane, l);
    }
    CPASYNC_WAIT();
    __syncthreads();

    // ---------- tensor phase: t, r, l back-to-back; B prefetched one ahead ----------
    copy_b_async(smem, tid, 1, B1);                       // B_r under gemm_t
    gemm_phase(sb, A_T, B0, warp_m, warp_n, lane, acc);
    CPASYNC_WAIT();
    __syncthreads();

    copy_b_async(smem, tid, 2, B0);                       // B_l under gemm_r
    gemm_phase(sb, A_R, B1, warp_m, warp_n, lane, acc);
    CPASYNC_WAIT();
    __syncthreads();

    gemm_phase(sb, A_L, B0, warp_m, warp_n, lane, acc);

    // ---------- epilogue: bias + relu + store ----------
#pragma unroll
    for (int mt = 0; mt < 2; ++mt) {
#pragma unroll
        for (int i = 0; i < 2; ++i) {
            const int m = gn0 + warp_m + mt * 16 + (lane >> 2) + i * 8;
            float* orow = out + (size_t)m * OO;
#pragma unroll
            for (int nt = 0; nt < 4; ++nt) {
                const int n = warp_n + nt * 8 + (lane & 3) * 2;
                float2 o;
                o.x = fmaxf(acc[mt][nt][i * 2 + 0] + __ldg(bias + n),     0.f);
                o.y = fmaxf(acc[mt][nt][i * 2 + 1] + __ldg(bias + n + 1), 0.f);
                *reinterpret_cast<float2*>(orow + n) = o;
            }
        }
    }
}

extern "C" void kernel_launch(void* const* d_in, const int* in_sizes, int n_in,
                              void* d_out, int out_size) {
    const float* nodes    = (const float*)d_in[0];   // [B,N,F]
    const int*   children = (const int*)  d_in[1];   // [B,N,C]
    const float* w_t      = (const float*)d_in[2];   // [F,O]
    const float* w_l      = (const float*)d_in[3];   // [F,O]
    const float* w_r      = (const float*)d_in[4];   // [F,O]
    const float* bias     = (const float*)d_in[5];   // [O]
    float* out = (float*)d_out;                      // [B,N,O]

    prep_w<<<3, 256>>>(w_t, w_l, w_r);

    cudaFuncSetAttribute(btconv_mma_kernel, cudaFuncAttributeMaxDynamicSharedMemorySize, SM_TOTAL);
    const int grid = (BATCH * NN) / MT;              // 512 blocks
    btconv_mma_kernel<<<grid, NTHREADS, SM_TOTAL>>>(nodes, children, bias, out);
}

// round 7
// speedup vs baseline: 5.9341x; 1.2499x over previous
#include <cuda_runtime.h>
#include <cuda_fp16.h>
#include <cstdint>

#define BATCH 32
#define NN    2048
#define CC    8
#define FF    128
#define OO    128
#define MT    64               // nodes per tile
#define NTILES 1024            // (BATCH*NN)/MT
#define GRID   148
#define NTHREADS 512

// ---- smem layout (bytes) ----
// A(buf,term): 2 bufs x 3 terms x 16KB   = 96KB
// B(term):     3 x 32KB (resident)       = 96KB
#define SM_A(buf, term) ((buf) * 49152 + (term) * 16384)
#define SM_B(term)      (98304 + (term) * 32768)
#define SM_TOTAL        196608

// Pre-swizzled W images: [term(t,r,l)][128 n-rows x 128 k-cols fp16, swizzled]
__device__ __align__(16) unsigned char g_wimg[3][128 * 128 * 2];

// swizzled byte offset of (row, k) in a [row][k] fp16 tile with 256B rows
__device__ __host__ __forceinline__ uint32_t tile_off(int row, int k) {
    return (uint32_t)(row * 256 + ((((k >> 3) & 15) ^ (row & 7)) << 4) + (k & 7) * 2);
}

__device__ __forceinline__ uint32_t smem_u32(const void* p) {
    uint32_t a;
    asm("{ .reg .u64 t; cvta.to.shared.u64 t, %1; cvt.u32.u64 %0, t; }" : "=r"(a) : "l"(p));
    return a;
}
__device__ __forceinline__ void ldsm4(uint32_t* r, uint32_t addr) {
    asm volatile("ldmatrix.sync.aligned.m8n8.x4.shared.b16 {%0,%1,%2,%3}, [%4];"
        : "=r"(r[0]), "=r"(r[1]), "=r"(r[2]), "=r"(r[3]) : "r"(addr));
}
__device__ __forceinline__ void mma16816(float* d, const uint32_t* a, const uint32_t* b) {
    asm volatile("mma.sync.aligned.m16n8k16.row.col.f32.f16.f16.f32 "
        "{%0,%1,%2,%3}, {%4,%5,%6,%7}, {%8,%9}, {%0,%1,%2,%3};"
        : "+f"(d[0]), "+f"(d[1]), "+f"(d[2]), "+f"(d[3])
        : "r"(a[0]), "r"(a[1]), "r"(a[2]), "r"(a[3]), "r"(b[0]), "r"(b[1]));
}
__device__ __forceinline__ void store_h4(char* smem, int base, int m, int k4, float4 v) {
    const uint32_t off = tile_off(m, k4 * 4);
    __half2 h0 = __halves2half2(__float2half_rn(v.x), __float2half_rn(v.y));
    __half2 h1 = __halves2half2(__float2half_rn(v.z), __float2half_rn(v.w));
    uint2 u;
    u.x = *reinterpret_cast<uint32_t*>(&h0);
    u.y = *reinterpret_cast<uint32_t*>(&h1);
    *reinterpret_cast<uint2*>(smem + base + off) = u;
}

// ---------------- prep: W -> swizzled fp16 images (B stored [n][k]) ----------------
__global__ void prep_w(const float* __restrict__ w_t,
                       const float* __restrict__ w_l,
                       const float* __restrict__ w_r)
{
    const int term = blockIdx.x;                       // 0=t 1=r 2=l
    const float* src = (term == 0) ? w_t : (term == 1) ? w_r : w_l;
    for (int idx = threadIdx.x; idx < 128 * 128; idx += blockDim.x) {
        const int n = idx >> 7, k = idx & 127;
        const float v = src[(size_t)k * OO + n];       // B[n][k] = W[k][n]
        *reinterpret_cast<__half*>(&g_wimg[term][tile_off(n, k)]) = __float2half_rn(v);
    }
}

// ---------------- main kernel ----------------
__device__ __forceinline__ void copy_b_async(char* smem, int tid) {
#pragma unroll
    for (int i = 0; i < 12; ++i) {
        const int idx  = tid + i * NTHREADS;    // 0..6143 uint4
        const int term = idx >> 11;
        const int q    = idx & 2047;
        const uint32_t d = smem_u32(smem + SM_B(term) + q * 16);
        const void* src = &g_wimg[term][q * 16];
        asm volatile("cp.async.cg.shared.global [%0], [%1], 16;" :: "r"(d), "l"(src) : "memory");
    }
    asm volatile("cp.async.commit_group;" ::: "memory");
}
#define CPASYNC_WAIT() asm volatile("cp.async.wait_group 0;" ::: "memory")

// build the three 64x128 A tiles (x, agg_r, agg_l) for one tile into buffer `buf`
__device__ __forceinline__ void build_tile(char* smem, int buf, int tile,
                                           const float* __restrict__ nodes,
                                           const int*   __restrict__ children,
                                           int wid, int lane)
{
    const int gn0 = tile * MT;
    const int b   = gn0 >> 11;                 // / NN
    const int n0  = gn0 - b * NN;
    const float* __restrict__ nodesB = nodes + (size_t)b * NN * FF;

#pragma unroll
    for (int p = 0; p < 4; ++p) {
        const int m = wid * 4 + p;             // 0..63
        const float4 xv = *reinterpret_cast<const float4*>(
            nodesB + (size_t)(n0 + m) * FF + lane * 4);
        store_h4(smem, SM_A(buf, 0), m, lane, xv);

        const int* chp = children + (size_t)(gn0 + m) * CC;
        int ch[CC];
        int ns = 0;
#pragma unroll
        for (int c = 0; c < CC; ++c) { ch[c] = chp[c]; ns += (ch[c] != 0); }
        const float rdenom = (ns > 1) ? __frcp_rn((float)ns - 1.0f) : 0.0f;
        float crv[CC], clv[CC];
#pragma unroll
        for (int c = 0; c < CC; ++c) {
            const float mfl = (ch[c] != 0) ? 1.0f : 0.0f;
            float cr;
            if (ns == 1) cr = (c == 0) ? 0.5f : 0.0f;
            else         cr = (float)c * mfl * rdenom;
            crv[c] = cr * mfl;
            clv[c] = (1.0f - cr) * mfl;
        }
        float4 r; r.x = r.y = r.z = r.w = 0.f;
        float4 l; l.x = l.y = l.z = l.w = 0.f;
        const float* base = nodesB + lane * 4;
#pragma unroll
        for (int c = 0; c < CC; ++c) {
            const float4 v = *reinterpret_cast<const float4*>(base + (size_t)ch[c] * FF);
            r.x += crv[c] * v.x; r.y += crv[c] * v.y; r.z += crv[c] * v.z; r.w += crv[c] * v.w;
            l.x += clv[c] * v.x; l.y += clv[c] * v.y; l.z += clv[c] * v.z; l.w += clv[c] * v.w;
        }
        store_h4(smem, SM_A(buf, 1), m, lane, r);
        store_h4(smem, SM_A(buf, 2), m, lane, l);
    }
}

// one GEMM phase: A tile at a_off (64x128), B term at b_off; warp tile 16m x 32n
__device__ __forceinline__ void gemm_phase(uint32_t sb, int a_off, int b_off,
                                           uint32_t a_base, uint32_t a_sx, uint32_t a_cadd,
                                           const uint32_t* b_base, const uint32_t* b_sx,
                                           uint32_t b_cadd, float acc[4][4])
{
#pragma unroll
    for (int ks = 0; ks < 8; ++ks) {
        uint32_t af[4], bf[2][4];
        const uint32_t ac = a_base + ((((uint32_t)(ks * 2) + a_cadd) ^ a_sx) << 4);
        ldsm4(af, sb + a_off + ac);
#pragma unroll
        for (int np = 0; np < 2; ++np) {
            const uint32_t bc = b_base[np] + ((((uint32_t)(ks * 2) + b_cadd) ^ b_sx[np]) << 4);
            ldsm4(bf[np], sb + b_off + bc);
        }
#pragma unroll
        for (int np = 0; np < 2; ++np)
#pragma unroll
            for (int ns = 0; ns < 2; ++ns)
                mma16816(acc[np * 2 + ns], af, bf[np] + ns * 2);
    }
}

__global__ void __launch_bounds__(NTHREADS, 1)
btconv_mma_kernel(const float* __restrict__ nodes,
                  const int*   __restrict__ children,
                  const float* __restrict__ bias,
                  float*       __restrict__ out)
{
    extern __shared__ char smem[];
    const uint32_t sb = smem_u32(smem);
    const int tid  = threadIdx.x;
    const int wid  = tid >> 5;       // 0..15
    const int lane = tid & 31;

    const int warp_m = (wid & 3) * 16;
    const int warp_n = (wid >> 2) * 32;

    // fragment addressing constants
    const int am = warp_m + (lane & 15);
    const uint32_t a_base = (uint32_t)(am * 256);
    const uint32_t a_sx   = (uint32_t)(am & 7);
    const uint32_t a_cadd = (uint32_t)(lane >> 4);
    uint32_t b_base[2], b_sx[2];
#pragma unroll
    for (int np = 0; np < 2; ++np) {
        const int n = warp_n + np * 16 + (lane & 7) + ((lane >> 4) << 3);
        b_base[np] = (uint32_t)(n * 256);
        b_sx[np]   = (uint32_t)(n & 7);
    }
    const uint32_t b_cadd = (uint32_t)((lane >> 3) & 1);

    // bias (per-thread output columns)
    float bv[8];
#pragma unroll
    for (int nt = 0; nt < 4; ++nt) {
        const int n = warp_n + nt * 8 + (lane & 3) * 2;
        bv[nt * 2 + 0] = __ldg(bias + n);
        bv[nt * 2 + 1] = __ldg(bias + n + 1);
    }

    // stage resident B + build first tile
    copy_b_async(smem, tid);
    int tile = blockIdx.x;
    build_tile(smem, 0, tile, nodes, children, wid, lane);
    CPASYNC_WAIT();
    __syncthreads();

    int buf = 0;
    while (true) {
        const int tnext = tile + GRID;
        if (tnext < NTILES)
            build_tile(smem, buf ^ 1, tnext, nodes, children, wid, lane);

        // GEMM: 3 terms back-to-back, accumulate
        float acc[4][4];
#pragma unroll
        for (int j = 0; j < 4; ++j)
#pragma unroll
            for (int q = 0; q < 4; ++q) acc[j][q] = 0.f;
#pragma unroll
        for (int term = 0; term < 3; ++term)
            gemm_phase(sb, SM_A(buf, term), SM_B(term),
                       a_base, a_sx, a_cadd, b_base, b_sx, b_cadd, acc);

        // epilogue: bias + relu + store
        const int gn0 = tile * MT;
#pragma unroll
        for (int i = 0; i < 2; ++i) {
            const int m = gn0 + warp_m + (lane >> 2) + i * 8;
            float* orow = out + (size_t)m * OO;
#pragma unroll
            for (int nt = 0; nt < 4; ++nt) {
                const int n = warp_n + nt * 8 + (lane & 3) * 2;
                float2 o;
                o.x = fmaxf(acc[nt][i * 2 + 0] + bv[nt * 2 + 0], 0.f);
                o.y = fmaxf(acc[nt][i * 2 + 1] + bv[nt * 2 + 1], 0.f);
                *reinterpret_cast<float2*>(orow + n) = o;
            }
        }

        if (tnext >= NTILES) break;
        tile = tnext;
        buf ^= 1;
        __syncthreads();
    }
}

extern "C" void kernel_launch(void* const* d_in, const int* in_sizes, int n_in,
                              void* d_out, int out_size) {
    const float* nodes    = (const float*)d_in[0];   // [B,N,F]
    const int*   children = (const int*)  d_in[1];   // [B,N,C]
    const float* w_t      = (const float*)d_in[2];   // [F,O]
    const float* w_l      = (const float*)d_in[3];   // [F,O]
    const float* w_r      = (const float*)d_in[4];   // [F,O]
    const float* bias     = (const float*)d_in[5];   // [O]
    float* out = (float*)d_out;                      // [B,N,O]

    prep_w<<<3, 256>>>(w_t, w_l, w_r);

    cudaFuncSetAttribute(btconv_mma_kernel, cudaFuncAttributeMaxDynamicSharedMemorySize, SM_TOTAL);
    btconv_mma_kernel<<<GRID, NTHREADS, SM_TOTAL>>>(nodes, children, bias, out);
}

// round 8
// speedup vs baseline: 7.5271x; 1.2684x over previous
#include <cuda_runtime.h>
#include <cuda_fp16.h>
#include <cstdint>

#define BATCH 32
#define NN    2048
#define CC    8
#define FF    128
#define OO    128
#define MT    64               // nodes per tile
#define NTILES 1024            // (BATCH*NN)/MT
#define GRID   148
#define NTHREADS 512

// ---- smem layout (bytes) ----
// A(buf,term): 2 bufs x 3 terms x 16KB = 96KB ; B(term): 3 x 32KB = 96KB
#define SM_A(buf, term) ((buf) * 49152 + (term) * 16384)
#define SM_B(term)      (98304 + (term) * 32768)
#define SM_TOTAL        196608

// swizzled byte offset of (row, k) in a [row][k] fp16 tile with 256B rows
__device__ __forceinline__ uint32_t tile_off(int row, int k) {
    return (uint32_t)(row * 256 + ((((k >> 3) & 15) ^ (row & 7)) << 4) + (k & 7) * 2);
}

__device__ __forceinline__ uint32_t smem_u32(const void* p) {
    uint32_t a;
    asm("{ .reg .u64 t; cvta.to.shared.u64 t, %1; cvt.u32.u64 %0, t; }" : "=r"(a) : "l"(p));
    return a;
}
__device__ __forceinline__ void ldsm4(uint32_t* r, uint32_t addr) {
    asm volatile("ldmatrix.sync.aligned.m8n8.x4.shared.b16 {%0,%1,%2,%3}, [%4];"
        : "=r"(r[0]), "=r"(r[1]), "=r"(r[2]), "=r"(r[3]) : "r"(addr));
}
__device__ __forceinline__ void mma16816(float* d, const uint32_t* a, const uint32_t* b) {
    asm volatile("mma.sync.aligned.m16n8k16.row.col.f32.f16.f16.f32 "
        "{%0,%1,%2,%3}, {%4,%5,%6,%7}, {%8,%9}, {%0,%1,%2,%3};"
        : "+f"(d[0]), "+f"(d[1]), "+f"(d[2]), "+f"(d[3])
        : "r"(a[0]), "r"(a[1]), "r"(a[2]), "r"(a[3]), "r"(b[0]), "r"(b[1]));
}
__device__ __forceinline__ void store_h4(char* smem, int base, int m, int k4, float4 v) {
    const uint32_t off = tile_off(m, k4 * 4);
    __half2 h0 = __halves2half2(__float2half_rn(v.x), __float2half_rn(v.y));
    __half2 h1 = __halves2half2(__float2half_rn(v.z), __float2half_rn(v.w));
    uint2 u;
    u.x = *reinterpret_cast<uint32_t*>(&h0);
    u.y = *reinterpret_cast<uint32_t*>(&h1);
    *reinterpret_cast<uint2*>(smem + base + off) = u;
}

#define BAR_SYNC(id)   asm volatile("bar.sync %0, %1;"   :: "r"(id), "r"(NTHREADS) : "memory")
#define BAR_ARRIVE(id) asm volatile("bar.arrive %0, %1;" :: "r"(id), "r"(NTHREADS) : "memory")
#define MEMBAR_CTA()   asm volatile("membar.cta;" ::: "memory")

// build the three 64x128 A tiles (x, agg_r, agg_l) — producer warps (pw = 0..7)
__device__ __forceinline__ void build_tile(char* smem, int buf, int tile,
                                           const float* __restrict__ nodes,
                                           const int*   __restrict__ children,
                                           int pw, int lane)
{
    const int gn0 = tile * MT;
    const int b   = gn0 >> 11;                 // / NN
    const int n0  = gn0 - b * NN;
    const float* __restrict__ nodesB = nodes + (size_t)b * NN * FF;

#pragma unroll
    for (int p = 0; p < 8; ++p) {
        const int m = pw * 8 + p;              // 0..63
        const float4 xv = *reinterpret_cast<const float4*>(
            nodesB + (size_t)(n0 + m) * FF + lane * 4);
        store_h4(smem, SM_A(buf, 0), m, lane, xv);

        const int* chp = children + (size_t)(gn0 + m) * CC;
        int ch[CC];
        int ns = 0;
#pragma unroll
        for (int c = 0; c < CC; ++c) { ch[c] = chp[c]; ns += (ch[c] != 0); }
        const float rdenom = (ns > 1) ? __frcp_rn((float)ns - 1.0f) : 0.0f;
        float crv[CC], clv[CC];
#pragma unroll
        for (int c = 0; c < CC; ++c) {
            const float mfl = (ch[c] != 0) ? 1.0f : 0.0f;
            float cr;
            if (ns == 1) cr = (c == 0) ? 0.5f : 0.0f;
            else         cr = (float)c * mfl * rdenom;
            crv[c] = cr * mfl;
            clv[c] = (1.0f - cr) * mfl;
        }
        float4 r; r.x = r.y = r.z = r.w = 0.f;
        float4 l; l.x = l.y = l.z = l.w = 0.f;
        const float* base = nodesB + lane * 4;
#pragma unroll
        for (int c = 0; c < CC; ++c) {
            const float4 v = *reinterpret_cast<const float4*>(base + (size_t)ch[c] * FF);
            r.x += crv[c] * v.x; r.y += crv[c] * v.y; r.z += crv[c] * v.z; r.w += crv[c] * v.w;
            l.x += clv[c] * v.x; l.y += clv[c] * v.y; l.z += clv[c] * v.z; l.w += clv[c] * v.w;
        }
        store_h4(smem, SM_A(buf, 1), m, lane, r);
        store_h4(smem, SM_A(buf, 2), m, lane, l);
    }
}

__global__ void __launch_bounds__(NTHREADS, 1)
btconv_ws_kernel(const float* __restrict__ nodes,
                 const int*   __restrict__ children,
                 const float* __restrict__ w_t,
                 const float* __restrict__ w_l,
                 const float* __restrict__ w_r,
                 const float* __restrict__ bias,
                 float*       __restrict__ out)
{
    extern __shared__ char smem[];
    const uint32_t sb = smem_u32(smem);
    const int tid  = threadIdx.x;
    const int wid  = tid >> 5;       // 0..15
    const int lane = tid & 31;

    // ---------- B build (all 512 threads): W -> swizzled fp16 images [n][k] ----------
    for (int u = tid; u < 3 * 16 * 128; u += NTHREADS) {
        const int n    = u & 127;
        const int kg   = (u >> 7) & 15;        // k group of 8
        const int term = u >> 11;              // 0=t 1=r 2=l
        const float* src = (term == 0) ? w_t : (term == 1) ? w_r : w_l;  // W[k][n]
        float f[8];
#pragma unroll
        for (int j = 0; j < 8; ++j)
            f[j] = __ldg(src + (size_t)(kg * 8 + j) * OO + n);
        uint4 v;
        __half2 h;
        h = __halves2half2(__float2half_rn(f[0]), __float2half_rn(f[1])); v.x = *reinterpret_cast<uint32_t*>(&h);
        h = __halves2half2(__float2half_rn(f[2]), __float2half_rn(f[3])); v.y = *reinterpret_cast<uint32_t*>(&h);
        h = __halves2half2(__float2half_rn(f[4]), __float2half_rn(f[5])); v.z = *reinterpret_cast<uint32_t*>(&h);
        h = __halves2half2(__float2half_rn(f[6]), __float2half_rn(f[7])); v.w = *reinterpret_cast<uint32_t*>(&h);
        *reinterpret_cast<uint4*>(smem + SM_B(term) + tile_off(n, kg * 8)) = v;
    }
    __syncthreads();

    if (wid >= 8) {
        // ================= PRODUCER (warps 8..15) =================
        const int pw = wid - 8;
        int i = 0;
        for (int tile = blockIdx.x; tile < NTILES; tile += GRID, ++i) {
            const int buf = i & 1;
            if (i >= 2) BAR_SYNC(3 + buf);          // wait: consumers freed this buf
            build_tile(smem, buf, tile, nodes, children, pw, lane);
            MEMBAR_CTA();
            BAR_ARRIVE(1 + buf);                    // signal: buf ready
        }
    } else {
        // ================= CONSUMER (warps 0..7) =================
        const int warp_m = (wid & 1) * 32;
        const int warp_n = (wid >> 1) * 32;

        // fragment addressing constants
        uint32_t a_base[2], a_sx[2], b_base[2], b_sx[2];
#pragma unroll
        for (int mt = 0; mt < 2; ++mt) {
            const int m = warp_m + mt * 16 + (lane & 15);
            a_base[mt] = (uint32_t)(m * 256);
            a_sx[mt]   = (uint32_t)(m & 7);
        }
#pragma unroll
        for (int np = 0; np < 2; ++np) {
            const int n = warp_n + np * 16 + (lane & 7) + ((lane >> 4) << 3);
            b_base[np] = (uint32_t)(n * 256);
            b_sx[np]   = (uint32_t)(n & 7);
        }
        const uint32_t a_cadd = (uint32_t)(lane >> 4);
        const uint32_t b_cadd = (uint32_t)((lane >> 3) & 1);

        float bv[8];
#pragma unroll
        for (int nt = 0; nt < 4; ++nt) {
            const int n = warp_n + nt * 8 + (lane & 3) * 2;
            bv[nt * 2 + 0] = __ldg(bias + n);
            bv[nt * 2 + 1] = __ldg(bias + n + 1);
        }

        int i = 0;
        for (int tile = blockIdx.x; tile < NTILES; tile += GRID, ++i) {
            const int buf = i & 1;
            BAR_SYNC(1 + buf);                      // wait: buf ready

            float acc[2][4][4];
#pragma unroll
            for (int a = 0; a < 2; ++a)
#pragma unroll
                for (int j = 0; j < 4; ++j)
#pragma unroll
                    for (int q = 0; q < 4; ++q) acc[a][j][q] = 0.f;

#pragma unroll
            for (int term = 0; term < 3; ++term) {
                const int a_off = SM_A(buf, term);
                const int b_off = SM_B(term);
#pragma unroll
                for (int ks = 0; ks < 8; ++ks) {
                    uint32_t af[2][4], bf[2][4];
#pragma unroll
                    for (int mt = 0; mt < 2; ++mt) {
                        const uint32_t ac = a_base[mt] + ((((uint32_t)(ks * 2) + a_cadd) ^ a_sx[mt]) << 4);
                        ldsm4(af[mt], sb + a_off + ac);
                    }
#pragma unroll
                    for (int np = 0; np < 2; ++np) {
                        const uint32_t bc = b_base[np] + ((((uint32_t)(ks * 2) + b_cadd) ^ b_sx[np]) << 4);
                        ldsm4(bf[np], sb + b_off + bc);
                    }
#pragma unroll
                    for (int mt = 0; mt < 2; ++mt)
#pragma unroll
                        for (int np = 0; np < 2; ++np)
#pragma unroll
                            for (int ns = 0; ns < 2; ++ns)
                                mma16816(acc[mt][np * 2 + ns], af[mt], bf[np] + ns * 2);
                }
            }

            // release the buffer as soon as all ldsm done (before epilogue)
            if (tile + 2 * GRID < NTILES) BAR_ARRIVE(3 + buf);

            // epilogue: bias + relu + store
            const int gn0 = tile * MT;
#pragma unroll
            for (int mt = 0; mt < 2; ++mt) {
#pragma unroll
                for (int ii = 0; ii < 2; ++ii) {
                    const int m = gn0 + warp_m + mt * 16 + (lane >> 2) + ii * 8;
                    float* orow = out + (size_t)m * OO;
#pragma unroll
                    for (int nt = 0; nt < 4; ++nt) {
                        const int n = warp_n + nt * 8 + (lane & 3) * 2;
                        float2 o;
                        o.x = fmaxf(acc[mt][nt][ii * 2 + 0] + bv[nt * 2 + 0], 0.f);
                        o.y = fmaxf(acc[mt][nt][ii * 2 + 1] + bv[nt * 2 + 1], 0.f);
                        *reinterpret_cast<float2*>(orow + n) = o;
                    }
                }
            }
        }
    }
}

extern "C" void kernel_launch(void* const* d_in, const int* in_sizes, int n_in,
                              void* d_out, int out_size) {
    const float* nodes    = (const float*)d_in[0];   // [B,N,F]
    const int*   children = (const int*)  d_in[1];   // [B,N,C]
    const float* w_t      = (const float*)d_in[2];   // [F,O]
    const float* w_l      = (const float*)d_in[3];   // [F,O]
    const float* w_r      = (const float*)d_in[4];   // [F,O]
    const float* bias     = (const float*)d_in[5];   // [O]
    float* out = (float*)d_out;                      // [B,N,O]

    cudaFuncSetAttribute(btconv_ws_kernel, cudaFuncAttributeMaxDynamicSharedMemorySize, SM_TOTAL);
    btconv_ws_kernel<<<GRID, NTHREADS, SM_TOTAL>>>(nodes, children, w_t, w_l, w_r, bias, out);
}